// round 1
// baseline (speedup 1.0000x reference)
#include <cuda_runtime.h>
#include <math.h>

#define BB 32
#define NINPUT 1024
#define NN 1024
#define WL 64
#define RR 4
#define IFACE 471
#define DELTA 1e-6f

typedef unsigned long long u64;

// ---------------- scratch (static device memory; no allocation) ----------------
__device__ float g_rk_n[BB*RR*WL];   // normalized read keys
__device__ float g_rstr[BB*RR];      // softplus read strengths
__device__ float g_wk_n[BB*WL];      // normalized write key
__device__ float g_wstr[BB];         // softplus write strength
__device__ float g_erase[BB*WL];
__device__ float g_wv[BB*WL];
__device__ float g_fg[BB*RR];
__device__ float g_ag[BB];
__device__ float g_wg[BB];
__device__ float g_rm[BB*RR*3];
__device__ float g_simw[BB*NN];
__device__ float g_ww[BB*NN];
__device__ float g_Ldiag[BB*NN];
__device__ float g_S1[BB*RR*NN];
__device__ float g_S2[BB*RR*NN];
__device__ float g_T1[BB*RR*NN];
__device__ float g_T2[BB*RR*NN];
__device__ float g_nm[BB*NN*WL];     // new memory
__device__ float g_simr[BB*RR*NN];

// ---------------- helpers ----------------
__device__ __forceinline__ float sigmoidf_(float x){ return 1.f/(1.f+expf(-x)); }
__device__ __forceinline__ float softplusf_(float x){ return fmaxf(x,0.f)+log1pf(expf(-fabsf(x))); }

__device__ __forceinline__ u64 pack2(float a, float b){
    u64 r; asm("mov.b64 %0,{%1,%2};":"=l"(r):"f"(a),"f"(b)); return r;
}
__device__ __forceinline__ void unpack2(u64 v, float& a, float& b){
    asm("mov.b64 {%0,%1},%2;":"=f"(a),"=f"(b):"l"(v));
}
__device__ __forceinline__ void fma2(u64& d, u64 a, u64 b){
    asm("fma.rn.f32x2 %0,%1,%2,%0;":"+l"(d):"l"(a),"l"(b));
}
__device__ __forceinline__ u64 add2(u64 a, u64 b){
    u64 r; asm("add.rn.f32x2 %0,%1,%2;":"=l"(r):"l"(a),"l"(b)); return r;
}

// ================= K1: interface GEMV + activations =================
__global__ void k_iface(const float* __restrict__ x, const float* __restrict__ W,
                        const float* __restrict__ bias){
    int b = blockIdx.x; int t = threadIdx.x; // 512 threads
    __shared__ float xs[NINPUT];
    __shared__ float act[IFACE+1];
    __shared__ float norms[5];
    for (int k=t;k<NINPUT;k+=512) xs[k]=x[b*NINPUT+k];
    __syncthreads();
    if (t < IFACE){
        float acc = bias[t];
        #pragma unroll 8
        for (int k=0;k<NINPUT;k++) acc = fmaf(xs[k], W[k*IFACE+t], acc);
        float v;
        if (t < 256)       v = tanhf(acc);          // read keys
        else if (t < 260)  v = softplusf_(acc);     // read strengths
        else if (t < 324)  v = tanhf(acc);          // write key
        else if (t == 324) v = softplusf_(acc);     // write strength
        else if (t < 389)  v = sigmoidf_(acc);      // erase
        else if (t < 453)  v = tanhf(acc);          // write vector
        else if (t < 459)  v = sigmoidf_(acc);      // free gates + ag + wg
        else               v = acc;                 // read modes (raw)
        act[t] = v;
    }
    __syncthreads();
    if (t < 160){
        int g = t>>5, l = t&31;
        const float* base = (g<4)? (act + g*64) : (act + 260);
        float s = base[l]*base[l] + base[l+32]*base[l+32];
        #pragma unroll
        for (int m=16;m;m>>=1) s += __shfl_xor_sync(0xffffffffu, s, m);
        if (l==0) norms[g] = sqrtf(s) + DELTA;
    }
    __syncthreads();
    if (t < 256)       g_rk_n[b*256+t] = act[t] / norms[t>>6];
    else if (t < 260)  g_rstr[b*4 + (t-256)] = act[t];
    else if (t < 324)  g_wk_n[b*64 + (t-260)] = act[t] / norms[4];
    else if (t == 324) g_wstr[b] = act[t];
    else if (t < 389)  g_erase[b*64 + (t-325)] = act[t];
    else if (t < 453)  g_wv[b*64 + (t-389)] = act[t];
    else if (t < 457)  g_fg[b*4 + (t-453)] = act[t];
    else if (t == 457) g_ag[b] = act[t];
    else if (t == 458) g_wg[b] = act[t];
    if (t < 4){
        float a0=act[459+t*3], a1=act[460+t*3], a2=act[461+t*3];
        float mx=fmaxf(a0,fmaxf(a1,a2));
        float e0=expf(a0-mx), e1=expf(a1-mx), e2=expf(a2-mx);
        float inv=1.f/(e0+e1+e2);
        g_rm[b*12+t*3+0]=e0*inv; g_rm[b*12+t*3+1]=e1*inv; g_rm[b*12+t*3+2]=e2*inv;
    }
}

// ================= K2: write content similarity =================
__global__ void k_simw(const float* __restrict__ mem){
    int b = blockIdx.x;
    int wid = threadIdx.x>>5, lane = threadIdx.x&31;
    int n = blockIdx.y*8 + wid;
    __shared__ float wk[64];
    if (threadIdx.x < 64) wk[threadIdx.x] = g_wk_n[b*64+threadIdx.x];
    __syncthreads();
    const float2* m2 = reinterpret_cast<const float2*>(mem + ((size_t)b*NN + n)*WL);
    float2 v = m2[lane];
    int w0 = 2*lane;
    float nsq = v.x*v.x + v.y*v.y;
    float dot = v.x*wk[w0] + v.y*wk[w0+1];
    #pragma unroll
    for (int m=16;m;m>>=1){
        nsq += __shfl_xor_sync(0xffffffffu,nsq,m);
        dot += __shfl_xor_sync(0xffffffffu,dot,m);
    }
    if (lane==0) g_simw[b*NN+n] = dot / (sqrtf(nsq)+DELTA);
}

// ================= K3: usage/sort/allocation/write weights =================
__global__ void k_alloc(const float* __restrict__ usage, const float* __restrict__ wwold,
                        const float* __restrict__ rw, const float* __restrict__ link){
    int b = blockIdx.x; int t = threadIdx.x; // 1024 threads
    __shared__ float sbuf[NN];
    __shared__ int   ibuf[NN];
    __shared__ float tbuf[NN];
    __shared__ float red[32];
    float us = usage[b*NN+t];
    float u = us + (1.f-us)*wwold[b*NN+t];
    float psi = 1.f;
    #pragma unroll
    for (int r=0;r<4;r++) psi *= (1.f - g_fg[b*4+r]*rw[(b*4+r)*NN+t]);
    u *= psi;
    u = DELTA + (1.f-DELTA)*u;
    sbuf[t]=u; ibuf[t]=t;
    __syncthreads();
    // bitonic sort ascending (value, index)
    for (int k=2;k<=NN;k<<=1){
        for (int j=k>>1;j>0;j>>=1){
            int ixj = t ^ j;
            if (ixj > t){
                float a=sbuf[t], c=sbuf[ixj];
                bool asc = ((t & k)==0);
                if ((a>c)==asc){
                    sbuf[t]=c; sbuf[ixj]=a;
                    int ia=ibuf[t]; ibuf[t]=ibuf[ixj]; ibuf[ixj]=ia;
                }
            }
            __syncthreads();
        }
    }
    float sv = sbuf[t];
    // inclusive multiplicative scan (Hillis-Steele)
    tbuf[t]=sv;
    __syncthreads();
    for (int off=1; off<NN; off<<=1){
        float w = (t>=off)? tbuf[t-off] : 1.f;
        __syncthreads();
        tbuf[t] *= w;
        __syncthreads();
    }
    float excl = (t==0)? 1.f : tbuf[t-1];
    __syncthreads();
    // scatter allocation back to original order
    tbuf[ibuf[t]] = (1.f - sv)*excl;
    // write content weighting softmax
    float beta = g_wstr[b];
    float s = g_simw[b*NN+t]*beta;
    float m = s;
    #pragma unroll
    for (int mm=16;mm;mm>>=1) m = fmaxf(m, __shfl_xor_sync(0xffffffffu,m,mm));
    __syncthreads();
    if ((t&31)==0) red[t>>5]=m;
    __syncthreads();
    if (t==0){ float z=red[0]; for (int i=1;i<32;i++) z=fmaxf(z,red[i]); red[0]=z; }
    __syncthreads();
    m = red[0];
    float e = expf(s-m);
    float ssum = e;
    #pragma unroll
    for (int mm=16;mm;mm>>=1) ssum += __shfl_xor_sync(0xffffffffu,ssum,mm);
    __syncthreads();
    if ((t&31)==0) red[t>>5]=ssum;
    __syncthreads();
    if (t==0){ float z=0.f; for (int i=0;i<32;i++) z+=red[i]; red[0]=z; }
    __syncthreads();
    float wcw = e/red[0];
    float ag = g_ag[b], wg = g_wg[b];
    g_ww[b*NN+t] = wg*(ag*tbuf[t] + (1.f-ag)*wcw);
    g_Ldiag[b*NN+t] = link[((size_t)b*NN + t)*NN + t];
}

// ================= K4: fused link matvecs (S row-sums + T col-sums) =================
// grid = 512 blocks; per batch: 8 S-role blocks (128-row strips) + 8 T-role blocks
// (128-col strips), interleaved so both read L[b] in the same window (L2 reuse).
__global__ void __launch_bounds__(256) k_linkmv(const float* __restrict__ link,
                                                const float* __restrict__ rw){
    int blk = blockIdx.x;
    int b = blk >> 4, sub = blk & 15;
    int t = threadIdx.x;
    __shared__ __align__(16) u64 coefp[NN][4]; // [0]=(rw0,rw1) [1]=(rw2,rw3) [2]=(cw0,cw1) [3]=(cw2,cw3)
    __shared__ float tred[128*8];
    for (int n=t;n<NN;n+=256){
        float r0=rw[(b*4+0)*NN+n], r1=rw[(b*4+1)*NN+n];
        float r2=rw[(b*4+2)*NN+n], r3=rw[(b*4+3)*NN+n];
        float w = g_ww[b*NN+n];
        coefp[n][0]=pack2(r0,r1); coefp[n][1]=pack2(r2,r3);
        coefp[n][2]=pack2(r0*w,r1*w); coefp[n][3]=pack2(r2*w,r3*w);
    }
    __syncthreads();
    const float* Lb = link + (size_t)b*NN*NN;
    if (sub < 8){
        // ---- S role: S1[r,i]=sum_j L[i,j] rw[r,j]; S2 with ww_j*rw ----
        int wid=t>>5, lane=t&31;
        for (int q=0;q<4;q++){
            int i0 = sub*128 + wid*16 + q*4;
            u64 acc[4][4];
            #pragma unroll
            for (int a=0;a<4;a++)
                #pragma unroll
                for (int c=0;c<4;c++) acc[a][c]=0ull;
            const float* L0 = Lb + (size_t)i0*NN;
            #pragma unroll 2
            for (int it=0; it<32; it++){
                int j = it*32 + lane;
                ulonglong2 ca = *reinterpret_cast<const ulonglong2*>(&coefp[j][0]);
                ulonglong2 cb = *reinterpret_cast<const ulonglong2*>(&coefp[j][2]);
                float lv[4];
                lv[0]=L0[j]; lv[1]=L0[j+NN]; lv[2]=L0[j+2*NN]; lv[3]=L0[j+3*NN];
                #pragma unroll
                for (int row=0;row<4;row++){
                    u64 p = pack2(lv[row], lv[row]);
                    fma2(acc[row][0], p, ca.x); fma2(acc[row][1], p, ca.y);
                    fma2(acc[row][2], p, cb.x); fma2(acc[row][3], p, cb.y);
                }
            }
            #pragma unroll
            for (int row=0;row<4;row++)
                #pragma unroll
                for (int c=0;c<4;c++)
                    #pragma unroll
                    for (int m=16;m;m>>=1)
                        acc[row][c] = add2(acc[row][c], __shfl_xor_sync(0xffffffffu, acc[row][c], m));
            if (lane==0){
                #pragma unroll
                for (int row=0;row<4;row++){
                    int i = i0+row;
                    float lo,hi;
                    unpack2(acc[row][0],lo,hi); g_S1[(b*4+0)*NN+i]=lo; g_S1[(b*4+1)*NN+i]=hi;
                    unpack2(acc[row][1],lo,hi); g_S1[(b*4+2)*NN+i]=lo; g_S1[(b*4+3)*NN+i]=hi;
                    unpack2(acc[row][2],lo,hi); g_S2[(b*4+0)*NN+i]=lo; g_S2[(b*4+1)*NN+i]=hi;
                    unpack2(acc[row][3],lo,hi); g_S2[(b*4+2)*NN+i]=lo; g_S2[(b*4+3)*NN+i]=hi;
                }
            }
        }
    } else {
        // ---- T role: T1[r,j]=sum_i L[i,j] rw[r,i]; T2 with ww_i*rw ----
        int tb = sub-8, j0 = tb*128;
        int c = t & 127, half = t>>7;
        u64 t1a=0ull,t1b=0ull,t2a=0ull,t2b=0ull;
        const float* Lc = Lb + j0 + c;
        int ibeg = half*512;
        #pragma unroll 4
        for (int ii=0; ii<512; ii++){
            int i = ibeg+ii;
            float lv = Lc[(size_t)i*NN];
            ulonglong2 ca = *reinterpret_cast<const ulonglong2*>(&coefp[i][0]);
            ulonglong2 cb = *reinterpret_cast<const ulonglong2*>(&coefp[i][2]);
            u64 p = pack2(lv,lv);
            fma2(t1a,p,ca.x); fma2(t1b,p,ca.y); fma2(t2a,p,cb.x); fma2(t2b,p,cb.y);
        }
        if (half==1){
            float f0,f1;
            unpack2(t1a,f0,f1); tred[c*8+0]=f0; tred[c*8+1]=f1;
            unpack2(t1b,f0,f1); tred[c*8+2]=f0; tred[c*8+3]=f1;
            unpack2(t2a,f0,f1); tred[c*8+4]=f0; tred[c*8+5]=f1;
            unpack2(t2b,f0,f1); tred[c*8+6]=f0; tred[c*8+7]=f1;
        }
        __syncthreads();
        if (half==0){
            float v[8], f0,f1;
            unpack2(t1a,f0,f1); v[0]=f0; v[1]=f1;
            unpack2(t1b,f0,f1); v[2]=f0; v[3]=f1;
            unpack2(t2a,f0,f1); v[4]=f0; v[5]=f1;
            unpack2(t2b,f0,f1); v[6]=f0; v[7]=f1;
            #pragma unroll
            for (int k=0;k<8;k++) v[k] += tred[c*8+k];
            int j = j0+c;
            g_T1[(b*4+0)*NN+j]=v[0]; g_T1[(b*4+1)*NN+j]=v[1];
            g_T1[(b*4+2)*NN+j]=v[2]; g_T1[(b*4+3)*NN+j]=v[3];
            g_T2[(b*4+0)*NN+j]=v[4]; g_T2[(b*4+1)*NN+j]=v[5];
            g_T2[(b*4+2)*NN+j]=v[6]; g_T2[(b*4+3)*NN+j]=v[7];
        }
    }
}

// ================= K5: new memory + read content sims =================
__global__ void k_newmem(const float* __restrict__ mem){
    int b = blockIdx.x;
    int wid = threadIdx.x>>5, lane = threadIdx.x&31;
    int n = blockIdx.y*8 + wid;
    int t = threadIdx.x;
    __shared__ float er[64], wv[64], rk[256];
    if (t<64){ er[t]=g_erase[b*64+t]; wv[t]=g_wv[b*64+t]; }
    if (t<256) rk[t]=g_rk_n[b*256+t];
    __syncthreads();
    float wwn = g_ww[b*NN+n];
    const float2* m2 = reinterpret_cast<const float2*>(mem + ((size_t)b*NN+n)*WL);
    float2* o2 = reinterpret_cast<float2*>(g_nm + ((size_t)b*NN+n)*WL);
    float2 v = m2[lane];
    int w0 = 2*lane, w1 = w0+1;
    float nx = v.x*(1.f - wwn*er[w0]) + wwn*wv[w0];
    float ny = v.y*(1.f - wwn*er[w1]) + wwn*wv[w1];
    o2[lane] = make_float2(nx,ny);
    float nsq = nx*nx+ny*ny;
    float d0 = nx*rk[0*64+w0]+ny*rk[0*64+w1];
    float d1 = nx*rk[1*64+w0]+ny*rk[1*64+w1];
    float d2 = nx*rk[2*64+w0]+ny*rk[2*64+w1];
    float d3 = nx*rk[3*64+w0]+ny*rk[3*64+w1];
    #pragma unroll
    for (int m=16;m;m>>=1){
        nsq += __shfl_xor_sync(0xffffffffu,nsq,m);
        d0  += __shfl_xor_sync(0xffffffffu,d0,m);
        d1  += __shfl_xor_sync(0xffffffffu,d1,m);
        d2  += __shfl_xor_sync(0xffffffffu,d2,m);
        d3  += __shfl_xor_sync(0xffffffffu,d3,m);
    }
    if (lane==0){
        float inv = 1.f/(sqrtf(nsq)+DELTA);
        g_simr[(b*4+0)*NN+n]=d0*inv;
        g_simr[(b*4+1)*NN+n]=d1*inv;
        g_simr[(b*4+2)*NN+n]=d2*inv;
        g_simr[(b*4+3)*NN+n]=d3*inv;
    }
}

// ================= K6: fwd/bwd assembly + crw softmax + read vectors =================
__device__ __forceinline__ float blockSum256(float v, float* red){
    int t=threadIdx.x;
    #pragma unroll
    for (int m=16;m;m>>=1) v += __shfl_xor_sync(0xffffffffu,v,m);
    __syncthreads();
    if ((t&31)==0) red[t>>5]=v;
    __syncthreads();
    if (t==0){ float z=0.f; for (int i=0;i<8;i++) z+=red[i]; red[0]=z; }
    __syncthreads();
    float r = red[0];
    __syncthreads();
    return r;
}
__device__ __forceinline__ float blockMax256(float v, float* red){
    int t=threadIdx.x;
    #pragma unroll
    for (int m=16;m;m>>=1) v = fmaxf(v, __shfl_xor_sync(0xffffffffu,v,m));
    __syncthreads();
    if ((t&31)==0) red[t>>5]=v;
    __syncthreads();
    if (t==0){ float z=red[0]; for (int i=1;i<8;i++) z=fmaxf(z,red[i]); red[0]=z; }
    __syncthreads();
    float r = red[0];
    __syncthreads();
    return r;
}

__global__ void __launch_bounds__(256) k_read(const float* __restrict__ prec,
                                              const float* __restrict__ rw,
                                              float* __restrict__ out){
    int b = blockIdx.x, r = blockIdx.y;
    int t = threadIdx.x;
    int br = b*4+r;
    __shared__ float nrw[NN];
    __shared__ float pout[256];
    __shared__ float red[32];
    float s1[4],s2[4],t1[4],t2[4],wwv[4],pv[4],rv[4],ldv[4],sv[4];
    float beta = g_rstr[br];
    float dpart=0.f, epart=0.f, mpart=-1e30f;
    #pragma unroll
    for (int k=0;k<4;k++){
        int n = t + k*256;
        s1[k]=g_S1[br*NN+n]; s2[k]=g_S2[br*NN+n];
        t1[k]=g_T1[br*NN+n]; t2[k]=g_T2[br*NN+n];
        wwv[k]=g_ww[b*NN+n]; pv[k]=prec[b*NN+n];
        rv[k]=rw[br*NN+n];   ldv[k]=g_Ldiag[b*NN+n];
        sv[k]=g_simr[br*NN+n]*beta;
        dpart += pv[k]*rv[k];
        epart += wwv[k]*rv[k];
        mpart = fmaxf(mpart, sv[k]);
    }
    float D = blockSum256(dpart, red);
    float E = blockSum256(epart, red);
    float M = blockMax256(mpart, red);
    float ex[4]; float spart=0.f;
    #pragma unroll
    for (int k=0;k<4;k++){ ex[k]=expf(sv[k]-M); spart+=ex[k]; }
    float S = blockSum256(spart, red);
    float invS = 1.f/S;
    float rm0=g_rm[b*12+r*3+0], rm1=g_rm[b*12+r*3+1], rm2=g_rm[b*12+r*3+2];
    #pragma unroll
    for (int k=0;k<4;k++){
        int n = t + k*256;
        float w = wwv[k];
        float diag = ((1.f-2.f*w)*ldv[k] + w*pv[k])*rv[k];
        float fwd = (1.f-w)*s1[k] - s2[k] + w*D - diag;
        float bwd = (1.f-w)*t1[k] - t2[k] + pv[k]*E - diag;
        float crw = ex[k]*invS;
        nrw[n] = rm0*bwd + rm1*crw + rm2*fwd;
    }
    __syncthreads();
    // read_vectors[b,r,w] = sum_n nrw[n] * new_memory[b,n,w]
    int w = t & 63, chunk = t >> 6;
    const float* nm = g_nm + (size_t)b*NN*WL;
    float acc = 0.f;
    int n0 = chunk*256;
    #pragma unroll 4
    for (int n=n0; n<n0+256; n++) acc = fmaf(nrw[n], nm[(size_t)n*WL + w], acc);
    pout[t]=acc;
    __syncthreads();
    if (t<64) out[br*64+t] = pout[t]+pout[64+t]+pout[128+t]+pout[192+t];
}

// ================= launch =================
extern "C" void kernel_launch(void* const* d_in, const int* in_sizes, int n_in,
                              void* d_out, int out_size){
    const float* x     = (const float*)d_in[0];
    const float* W     = (const float*)d_in[1];
    const float* bias  = (const float*)d_in[2];
    const float* mem   = (const float*)d_in[3];
    const float* link  = (const float*)d_in[4];
    const float* prec  = (const float*)d_in[5];
    const float* rw    = (const float*)d_in[6];
    const float* wwold = (const float*)d_in[7];
    const float* usage = (const float*)d_in[8];
    float* out = (float*)d_out;

    k_iface<<<BB, 512>>>(x, W, bias);
    k_simw<<<dim3(BB,128), 256>>>(mem);
    k_alloc<<<BB, 1024>>>(usage, wwold, rw, link);
    k_linkmv<<<BB*16, 256>>>(link, rw);
    k_newmem<<<dim3(BB,128), 256>>>(mem);
    k_read<<<dim3(BB,RR), 256>>>(prec, rw, out);
}

// round 2
// speedup vs baseline: 1.5755x; 1.5755x over previous
#include <cuda_runtime.h>
#include <math.h>

#define BB 32
#define NINPUT 1024
#define NN 1024
#define WL 64
#define RR 4
#define IFACE 471
#define OPAD 480
#define KSLICES 8
#define DELTA 1e-6f

typedef unsigned long long u64;

// ---------------- scratch (static device memory; no allocation) ----------------
__device__ float g_xi_part[KSLICES][BB][OPAD];
__device__ float g_rk_n[BB*RR*WL];
__device__ float g_rstr[BB*RR];
__device__ float g_wk_n[BB*WL];
__device__ float g_wstr[BB];
__device__ float g_erase[BB*WL];
__device__ float g_wv[BB*WL];
__device__ float g_fg[BB*RR];
__device__ float g_ag[BB];
__device__ float g_wg[BB];
__device__ float g_rm[BB*RR*3];
__device__ float g_simw[BB*NN];
__device__ float g_ww[BB*NN];
__device__ float g_Ldiag[BB*NN];
__device__ float g_S1[BB*RR*NN];
__device__ float g_S2[BB*RR*NN];
__device__ float g_T1[BB*RR*NN];
__device__ float g_T2[BB*RR*NN];
__device__ float g_nm[BB*NN*WL];
__device__ float g_simr[BB*RR*NN];

// ---------------- helpers ----------------
__device__ __forceinline__ float sigmoidf_(float x){ return 1.f/(1.f+expf(-x)); }
__device__ __forceinline__ float softplusf_(float x){ return fmaxf(x,0.f)+log1pf(expf(-fabsf(x))); }

__device__ __forceinline__ u64 pack2(float a, float b){
    u64 r; asm("mov.b64 %0,{%1,%2};":"=l"(r):"f"(a),"f"(b)); return r;
}
__device__ __forceinline__ void unpack2(u64 v, float& a, float& b){
    asm("mov.b64 {%0,%1},%2;":"=f"(a),"=f"(b):"l"(v));
}
__device__ __forceinline__ void fma2(u64& d, u64 a, u64 b){
    asm("fma.rn.f32x2 %0,%1,%2,%0;":"+l"(d):"l"(a),"l"(b));
}
__device__ __forceinline__ u64 add2(u64 a, u64 b){
    u64 r; asm("add.rn.f32x2 %0,%1,%2;":"=l"(r):"l"(a),"l"(b)); return r;
}

// ================= K1a: interface GEMM (tiled, k-sliced partials) =================
// grid (15, 8): blockIdx.x = output tile (32 outs), blockIdx.y = k slice (128 k)
__global__ void __launch_bounds__(256) k_gemm(const float* __restrict__ x,
                                              const float* __restrict__ W){
    int otile = blockIdx.x, ks = blockIdx.y;
    int t = threadIdx.x;
    __shared__ float ws[128][32];
    __shared__ float xs[32][128];
    int o0 = otile*32, k0 = ks*128;
    {   // W tile load: coalesced 32-wide rows
        int oo = t & 31, r0 = t >> 5;
        int o = o0 + oo;
        for (int r = r0; r < 128; r += 8)
            ws[r][oo] = (o < IFACE) ? W[(size_t)(k0 + r)*IFACE + o] : 0.f;
    }
    {   // x tile load
        int kk = t & 127, b0 = t >> 7;
        for (int b = b0; b < 32; b += 2)
            xs[b][kk] = x[b*NINPUT + k0 + kk];
    }
    __syncthreads();
    int p = t & 15;      // output pair index
    int bg = t >> 4;     // batch pair group
    int b0 = bg*2;
    u64 a0 = 0ull, a1 = 0ull;
    #pragma unroll 8
    for (int kk = 0; kk < 128; kk++){
        u64 wp = *reinterpret_cast<const u64*>(&ws[kk][p*2]);
        float xb0 = xs[b0][kk], xb1 = xs[b0+1][kk];
        fma2(a0, wp, pack2(xb0,xb0));
        fma2(a1, wp, pack2(xb1,xb1));
    }
    float f0,f1;
    unpack2(a0,f0,f1);
    g_xi_part[ks][b0  ][o0+p*2]=f0; g_xi_part[ks][b0  ][o0+p*2+1]=f1;
    unpack2(a1,f0,f1);
    g_xi_part[ks][b0+1][o0+p*2]=f0; g_xi_part[ks][b0+1][o0+p*2+1]=f1;
}

// ================= K1b: activations + normalization =================
__global__ void k_act(const float* __restrict__ bias){
    int b = blockIdx.x; int t = threadIdx.x; // 512 threads
    __shared__ float act[IFACE+1];
    __shared__ float norms[5];
    if (t < IFACE){
        float acc = bias[t];
        #pragma unroll
        for (int ks=0; ks<KSLICES; ks++) acc += g_xi_part[ks][b][t];
        float v;
        if (t < 256)       v = tanhf(acc);
        else if (t < 260)  v = softplusf_(acc);
        else if (t < 324)  v = tanhf(acc);
        else if (t == 324) v = softplusf_(acc);
        else if (t < 389)  v = sigmoidf_(acc);
        else if (t < 453)  v = tanhf(acc);
        else if (t < 459)  v = sigmoidf_(acc);
        else               v = acc;
        act[t] = v;
    }
    __syncthreads();
    if (t < 160){
        int g = t>>5, l = t&31;
        const float* base = (g<4)? (act + g*64) : (act + 260);
        float s = base[l]*base[l] + base[l+32]*base[l+32];
        #pragma unroll
        for (int m=16;m;m>>=1) s += __shfl_xor_sync(0xffffffffu, s, m);
        if (l==0) norms[g] = sqrtf(s) + DELTA;
    }
    __syncthreads();
    if (t < 256)       g_rk_n[b*256+t] = act[t] / norms[t>>6];
    else if (t < 260)  g_rstr[b*4 + (t-256)] = act[t];
    else if (t < 324)  g_wk_n[b*64 + (t-260)] = act[t] / norms[4];
    else if (t == 324) g_wstr[b] = act[t];
    else if (t < 389)  g_erase[b*64 + (t-325)] = act[t];
    else if (t < 453)  g_wv[b*64 + (t-389)] = act[t];
    else if (t < 457)  g_fg[b*4 + (t-453)] = act[t];
    else if (t == 457) g_ag[b] = act[t];
    else if (t == 458) g_wg[b] = act[t];
    if (t < 4){
        float a0=act[459+t*3], a1=act[460+t*3], a2=act[461+t*3];
        float mx=fmaxf(a0,fmaxf(a1,a2));
        float e0=expf(a0-mx), e1=expf(a1-mx), e2=expf(a2-mx);
        float inv=1.f/(e0+e1+e2);
        g_rm[b*12+t*3+0]=e0*inv; g_rm[b*12+t*3+1]=e1*inv; g_rm[b*12+t*3+2]=e2*inv;
    }
}

// ================= K2: write content similarity =================
__global__ void k_simw(const float* __restrict__ mem){
    int b = blockIdx.x;
    int wid = threadIdx.x>>5, lane = threadIdx.x&31;
    int n = blockIdx.y*8 + wid;
    __shared__ float wk[64];
    if (threadIdx.x < 64) wk[threadIdx.x] = g_wk_n[b*64+threadIdx.x];
    __syncthreads();
    const float2* m2 = reinterpret_cast<const float2*>(mem + ((size_t)b*NN + n)*WL);
    float2 v = m2[lane];
    int w0 = 2*lane;
    float nsq = v.x*v.x + v.y*v.y;
    float dot = v.x*wk[w0] + v.y*wk[w0+1];
    #pragma unroll
    for (int m=16;m;m>>=1){
        nsq += __shfl_xor_sync(0xffffffffu,nsq,m);
        dot += __shfl_xor_sync(0xffffffffu,dot,m);
    }
    if (lane==0) g_simw[b*NN+n] = dot / (sqrtf(nsq)+DELTA);
}

// ================= K3: usage/sort/allocation/write weights =================
__global__ void k_alloc(const float* __restrict__ usage, const float* __restrict__ wwold,
                        const float* __restrict__ rw, const float* __restrict__ link){
    int b = blockIdx.x; int t = threadIdx.x; // 1024 threads
    __shared__ float sbuf[NN];
    __shared__ int   ibuf[NN];
    __shared__ float tbuf[NN];
    __shared__ float red[32];
    float us = usage[b*NN+t];
    float u = us + (1.f-us)*wwold[b*NN+t];
    float psi = 1.f;
    #pragma unroll
    for (int r=0;r<4;r++) psi *= (1.f - g_fg[b*4+r]*rw[(b*4+r)*NN+t]);
    u *= psi;
    u = DELTA + (1.f-DELTA)*u;
    sbuf[t]=u; ibuf[t]=t;
    __syncthreads();
    for (int k=2;k<=NN;k<<=1){
        for (int j=k>>1;j>0;j>>=1){
            int ixj = t ^ j;
            if (ixj > t){
                float a=sbuf[t], c=sbuf[ixj];
                bool asc = ((t & k)==0);
                if ((a>c)==asc){
                    sbuf[t]=c; sbuf[ixj]=a;
                    int ia=ibuf[t]; ibuf[t]=ibuf[ixj]; ibuf[ixj]=ia;
                }
            }
            __syncthreads();
        }
    }
    float sv = sbuf[t];
    tbuf[t]=sv;
    __syncthreads();
    for (int off=1; off<NN; off<<=1){
        float w = (t>=off)? tbuf[t-off] : 1.f;
        __syncthreads();
        tbuf[t] *= w;
        __syncthreads();
    }
    float excl = (t==0)? 1.f : tbuf[t-1];
    __syncthreads();
    tbuf[ibuf[t]] = (1.f - sv)*excl;
    float beta = g_wstr[b];
    float s = g_simw[b*NN+t]*beta;
    float m = s;
    #pragma unroll
    for (int mm=16;mm;mm>>=1) m = fmaxf(m, __shfl_xor_sync(0xffffffffu,m,mm));
    __syncthreads();
    if ((t&31)==0) red[t>>5]=m;
    __syncthreads();
    if (t==0){ float z=red[0]; for (int i=1;i<32;i++) z=fmaxf(z,red[i]); red[0]=z; }
    __syncthreads();
    m = red[0];
    float e = expf(s-m);
    float ssum = e;
    #pragma unroll
    for (int mm=16;mm;mm>>=1) ssum += __shfl_xor_sync(0xffffffffu,ssum,mm);
    __syncthreads();
    if ((t&31)==0) red[t>>5]=ssum;
    __syncthreads();
    if (t==0){ float z=0.f; for (int i=0;i<32;i++) z+=red[i]; red[0]=z; }
    __syncthreads();
    float wcw = e/red[0];
    float ag = g_ag[b], wg = g_wg[b];
    g_ww[b*NN+t] = wg*(ag*tbuf[t] + (1.f-ag)*wcw);
    g_Ldiag[b*NN+t] = link[((size_t)b*NN + t)*NN + t];
}

// ================= K4: fused link matvecs =================
// grid = 1024: per batch 32 subs: even = S-role 64-row strip, odd = T-role 64-col strip
__global__ void __launch_bounds__(256) k_linkmv(const float* __restrict__ link,
                                                const float* __restrict__ rw){
    int blk = blockIdx.x;
    int b = blk >> 5, sub = blk & 31;
    int t = threadIdx.x;
    __shared__ u64 e01[NN], e23[NN], f01[NN], f23[NN]; // SoA packed coef, 32KB
    __shared__ float tred[3][64][8];
    for (int n=t;n<NN;n+=256){
        float r0=rw[(b*4+0)*NN+n], r1=rw[(b*4+1)*NN+n];
        float r2=rw[(b*4+2)*NN+n], r3=rw[(b*4+3)*NN+n];
        float w = g_ww[b*NN+n];
        e01[n]=pack2(r0,r1); e23[n]=pack2(r2,r3);
        f01[n]=pack2(r0*w,r1*w); f23[n]=pack2(r2*w,r3*w);
    }
    __syncthreads();
    const float* Lb = link + (size_t)b*NN*NN;
    int strip = sub >> 1;
    if ((sub & 1) == 0){
        // ---- S role: rows strip*64 .. +64 ----
        int wid=t>>5, lane=t&31;
        for (int g=0; g<2; g++){
            int i0 = strip*64 + wid*8 + g*4;
            u64 acc[4][4];
            #pragma unroll
            for (int a=0;a<4;a++)
                #pragma unroll
                for (int c=0;c<4;c++) acc[a][c]=0ull;
            const float* L0 = Lb + (size_t)i0*NN + lane;
            #pragma unroll 4
            for (int it=0; it<32; it++){
                int j = it*32 + lane;
                float lv0=L0[it*32];
                float lv1=L0[it*32+NN];
                float lv2=L0[it*32+2*NN];
                float lv3=L0[it*32+3*NN];
                u64 ca=e01[j], cb=e23[j], cc=f01[j], cd=f23[j];
                u64 p0=pack2(lv0,lv0), p1=pack2(lv1,lv1), p2=pack2(lv2,lv2), p3=pack2(lv3,lv3);
                fma2(acc[0][0],p0,ca); fma2(acc[0][1],p0,cb); fma2(acc[0][2],p0,cc); fma2(acc[0][3],p0,cd);
                fma2(acc[1][0],p1,ca); fma2(acc[1][1],p1,cb); fma2(acc[1][2],p1,cc); fma2(acc[1][3],p1,cd);
                fma2(acc[2][0],p2,ca); fma2(acc[2][1],p2,cb); fma2(acc[2][2],p2,cc); fma2(acc[2][3],p2,cd);
                fma2(acc[3][0],p3,ca); fma2(acc[3][1],p3,cb); fma2(acc[3][2],p3,cc); fma2(acc[3][3],p3,cd);
            }
            #pragma unroll
            for (int row=0;row<4;row++)
                #pragma unroll
                for (int c=0;c<4;c++)
                    #pragma unroll
                    for (int m=16;m;m>>=1)
                        acc[row][c] = add2(acc[row][c], __shfl_xor_sync(0xffffffffu, acc[row][c], m));
            if (lane==0){
                #pragma unroll
                for (int row=0;row<4;row++){
                    int i = i0+row;
                    float lo,hi;
                    unpack2(acc[row][0],lo,hi); g_S1[(b*4+0)*NN+i]=lo; g_S1[(b*4+1)*NN+i]=hi;
                    unpack2(acc[row][1],lo,hi); g_S1[(b*4+2)*NN+i]=lo; g_S1[(b*4+3)*NN+i]=hi;
                    unpack2(acc[row][2],lo,hi); g_S2[(b*4+0)*NN+i]=lo; g_S2[(b*4+1)*NN+i]=hi;
                    unpack2(acc[row][3],lo,hi); g_S2[(b*4+2)*NN+i]=lo; g_S2[(b*4+3)*NN+i]=hi;
                }
            }
        }
    } else {
        // ---- T role: cols strip*64 .. +64, rows split across 4 groups ----
        int j0 = strip*64;
        int c = t & 63, rg = t >> 6;
        u64 t1a=0ull,t1b=0ull,t2a=0ull,t2b=0ull;
        const float* Lc = Lb + (size_t)(rg*256)*NN + j0 + c;
        int ib = rg*256;
        #pragma unroll 8
        for (int ii=0; ii<256; ii++){
            float lv = Lc[(size_t)ii*NN];
            int i = ib + ii;
            u64 p = pack2(lv,lv);
            fma2(t1a,p,e01[i]); fma2(t1b,p,e23[i]);
            fma2(t2a,p,f01[i]); fma2(t2b,p,f23[i]);
        }
        if (rg>0){
            float f0,f1;
            unpack2(t1a,f0,f1); tred[rg-1][c][0]=f0; tred[rg-1][c][1]=f1;
            unpack2(t1b,f0,f1); tred[rg-1][c][2]=f0; tred[rg-1][c][3]=f1;
            unpack2(t2a,f0,f1); tred[rg-1][c][4]=f0; tred[rg-1][c][5]=f1;
            unpack2(t2b,f0,f1); tred[rg-1][c][6]=f0; tred[rg-1][c][7]=f1;
        }
        __syncthreads();
        if (rg==0){
            float v[8], f0,f1;
            unpack2(t1a,f0,f1); v[0]=f0; v[1]=f1;
            unpack2(t1b,f0,f1); v[2]=f0; v[3]=f1;
            unpack2(t2a,f0,f1); v[4]=f0; v[5]=f1;
            unpack2(t2b,f0,f1); v[6]=f0; v[7]=f1;
            #pragma unroll
            for (int g=0; g<3; g++)
                #pragma unroll
                for (int k=0;k<8;k++) v[k] += tred[g][c][k];
            int j = j0+c;
            g_T1[(b*4+0)*NN+j]=v[0]; g_T1[(b*4+1)*NN+j]=v[1];
            g_T1[(b*4+2)*NN+j]=v[2]; g_T1[(b*4+3)*NN+j]=v[3];
            g_T2[(b*4+0)*NN+j]=v[4]; g_T2[(b*4+1)*NN+j]=v[5];
            g_T2[(b*4+2)*NN+j]=v[6]; g_T2[(b*4+3)*NN+j]=v[7];
        }
    }
}

// ================= K5: new memory + read content sims =================
__global__ void k_newmem(const float* __restrict__ mem){
    int b = blockIdx.x;
    int wid = threadIdx.x>>5, lane = threadIdx.x&31;
    int n = blockIdx.y*8 + wid;
    int t = threadIdx.x;
    __shared__ float er[64], wv[64], rk[256];
    if (t<64){ er[t]=g_erase[b*64+t]; wv[t]=g_wv[b*64+t]; }
    if (t<256) rk[t]=g_rk_n[b*256+t];
    __syncthreads();
    float wwn = g_ww[b*NN+n];
    const float2* m2 = reinterpret_cast<const float2*>(mem + ((size_t)b*NN+n)*WL);
    float2* o2 = reinterpret_cast<float2*>(g_nm + ((size_t)b*NN+n)*WL);
    float2 v = m2[lane];
    int w0 = 2*lane, w1 = w0+1;
    float nx = v.x*(1.f - wwn*er[w0]) + wwn*wv[w0];
    float ny = v.y*(1.f - wwn*er[w1]) + wwn*wv[w1];
    o2[lane] = make_float2(nx,ny);
    float nsq = nx*nx+ny*ny;
    float d0 = nx*rk[0*64+w0]+ny*rk[0*64+w1];
    float d1 = nx*rk[1*64+w0]+ny*rk[1*64+w1];
    float d2 = nx*rk[2*64+w0]+ny*rk[2*64+w1];
    float d3 = nx*rk[3*64+w0]+ny*rk[3*64+w1];
    #pragma unroll
    for (int m=16;m;m>>=1){
        nsq += __shfl_xor_sync(0xffffffffu,nsq,m);
        d0  += __shfl_xor_sync(0xffffffffu,d0,m);
        d1  += __shfl_xor_sync(0xffffffffu,d1,m);
        d2  += __shfl_xor_sync(0xffffffffu,d2,m);
        d3  += __shfl_xor_sync(0xffffffffu,d3,m);
    }
    if (lane==0){
        float inv = 1.f/(sqrtf(nsq)+DELTA);
        g_simr[(b*4+0)*NN+n]=d0*inv;
        g_simr[(b*4+1)*NN+n]=d1*inv;
        g_simr[(b*4+2)*NN+n]=d2*inv;
        g_simr[(b*4+3)*NN+n]=d3*inv;
    }
}

// ================= K6: assembly + output =================
__device__ __forceinline__ float blockSum512(float v, float* red){
    int t=threadIdx.x;
    #pragma unroll
    for (int m=16;m;m>>=1) v += __shfl_xor_sync(0xffffffffu,v,m);
    __syncthreads();
    if ((t&31)==0) red[t>>5]=v;
    __syncthreads();
    if (t==0){ float z=0.f; for (int i=0;i<16;i++) z+=red[i]; red[0]=z; }
    __syncthreads();
    float r = red[0];
    __syncthreads();
    return r;
}
__device__ __forceinline__ float blockMax512(float v, float* red){
    int t=threadIdx.x;
    #pragma unroll
    for (int m=16;m;m>>=1) v = fmaxf(v, __shfl_xor_sync(0xffffffffu,v,m));
    __syncthreads();
    if ((t&31)==0) red[t>>5]=v;
    __syncthreads();
    if (t==0){ float z=red[0]; for (int i=1;i<16;i++) z=fmaxf(z,red[i]); red[0]=z; }
    __syncthreads();
    float r = red[0];
    __syncthreads();
    return r;
}

__global__ void __launch_bounds__(512) k_read(const float* __restrict__ prec,
                                              const float* __restrict__ rw,
                                              float* __restrict__ out){
    int b = blockIdx.x, r = blockIdx.y;
    int t = threadIdx.x;
    int br = b*4+r;
    __shared__ float nrw[NN];
    __shared__ float pout[512];
    __shared__ float red[16];
    float s1[2],s2[2],t1[2],t2[2],wwv[2],pv[2],rv[2],ldv[2],sv[2];
    float beta = g_rstr[br];
    float dpart=0.f, epart=0.f, mpart=-1e30f;
    #pragma unroll
    for (int k=0;k<2;k++){
        int n = t + k*512;
        s1[k]=g_S1[br*NN+n]; s2[k]=g_S2[br*NN+n];
        t1[k]=g_T1[br*NN+n]; t2[k]=g_T2[br*NN+n];
        wwv[k]=g_ww[b*NN+n]; pv[k]=prec[b*NN+n];
        rv[k]=rw[br*NN+n];   ldv[k]=g_Ldiag[b*NN+n];
        sv[k]=g_simr[br*NN+n]*beta;
        dpart += pv[k]*rv[k];
        epart += wwv[k]*rv[k];
        mpart = fmaxf(mpart, sv[k]);
    }
    float D = blockSum512(dpart, red);
    float E = blockSum512(epart, red);
    float M = blockMax512(mpart, red);
    float ex[2]; float spart=0.f;
    #pragma unroll
    for (int k=0;k<2;k++){ ex[k]=expf(sv[k]-M); spart+=ex[k]; }
    float S = blockSum512(spart, red);
    float invS = 1.f/S;
    float rm0=g_rm[b*12+r*3+0], rm1=g_rm[b*12+r*3+1], rm2=g_rm[b*12+r*3+2];
    #pragma unroll
    for (int k=0;k<2;k++){
        int n = t + k*512;
        float w = wwv[k];
        float diag = ((1.f-2.f*w)*ldv[k] + w*pv[k])*rv[k];
        float fwd = (1.f-w)*s1[k] - s2[k] + w*D - diag;
        float bwd = (1.f-w)*t1[k] - t2[k] + pv[k]*E - diag;
        float crw = ex[k]*invS;
        nrw[n] = rm0*bwd + rm1*crw + rm2*fwd;
    }
    __syncthreads();
    // read_vectors[b,r,w] = sum_n nrw[n] * new_memory[b,n,w]
    int w = t & 63, chunk = t >> 6;  // 8 chunks of 128 n each
    const float* nm = g_nm + (size_t)b*NN*WL;
    float a0=0.f,a1=0.f,a2=0.f,a3=0.f;
    int n0 = chunk*128;
    for (int n=n0; n<n0+128; n+=4){
        a0 = fmaf(nrw[n  ], nm[(size_t)(n  )*WL + w], a0);
        a1 = fmaf(nrw[n+1], nm[(size_t)(n+1)*WL + w], a1);
        a2 = fmaf(nrw[n+2], nm[(size_t)(n+2)*WL + w], a2);
        a3 = fmaf(nrw[n+3], nm[(size_t)(n+3)*WL + w], a3);
    }
    pout[t] = (a0+a1)+(a2+a3);
    __syncthreads();
    if (t < 64){
        float s = 0.f;
        #pragma unroll
        for (int c=0;c<8;c++) s += pout[c*64+t];
        out[br*64+t] = s;
    }
}

// ================= launch =================
extern "C" void kernel_launch(void* const* d_in, const int* in_sizes, int n_in,
                              void* d_out, int out_size){
    const float* x     = (const float*)d_in[0];
    const float* W     = (const float*)d_in[1];
    const float* bias  = (const float*)d_in[2];
    const float* mem   = (const float*)d_in[3];
    const float* link  = (const float*)d_in[4];
    const float* prec  = (const float*)d_in[5];
    const float* rw    = (const float*)d_in[6];
    const float* wwold = (const float*)d_in[7];
    const float* usage = (const float*)d_in[8];
    float* out = (float*)d_out;

    k_gemm<<<dim3(15, KSLICES), 256>>>(x, W);
    k_act<<<BB, 512>>>(bias);
    k_simw<<<dim3(BB,128), 256>>>(mem);
    k_alloc<<<BB, 1024>>>(usage, wwold, rw, link);
    k_linkmv<<<BB*32, 256>>>(link, rw);
    k_newmem<<<dim3(BB,128), 256>>>(mem);
    k_read<<<dim3(BB,RR), 512>>>(prec, rw, out);
}